// round 17
// baseline (speedup 1.0000x reference)
#include <cuda_runtime.h>
#include <cuda_fp16.h>
#include <math.h>

#define NN 50000
#define NE 1600000
#define DD 128
#define HH 8
#define NPART 8
#define NSLOT 64
#define LOG2E 1.44269504088896f

// ---------------- scratch (no allocations allowed) ----------------
__device__ __half2 g_xlh[NN * 64];     // x @ W in fp16 (256B per node row)
__device__ __half2 g_hh[NN * 64];      // pre-BN output (fp16)
__device__ float  g_asrc[NN * HH];     // pre-scaled by log2(e)
__device__ float  g_adst[NN * HH];     // pre-scaled by log2(e)
__device__ int    g_deg[NPART * NN];   // zero at load; re-zeroed by k_final each call
__device__ int    g_cur[NPART * NN];
__device__ int    g_rank[NE];
__device__ int    g_rowptr[NN + 1];
__device__ int    g_csrc[NE];
__device__ float  g_ps1[NSLOT * 128];  // BN partials (zeroed by k_final)
__device__ float  g_ps2[NSLOT * 128];
__device__ float  g_scale[DD];
__device__ float  g_shift[DD];
__device__ int    g_is64 = -1;         // first call self-detects

// ---------------- helpers ----------------
#define FMA2(d, a, b, c) \
    asm("fma.rn.f32x2 %0, %1, %2, %3;" : "=l"(d) : "l"(a), "l"(b), "l"(c))

__device__ __forceinline__ unsigned long long pk2(float v) {
    unsigned long long r;
    unsigned int u = __float_as_uint(v);
    asm("mov.b64 %0, {%1, %2};" : "=l"(r) : "r"(u), "r"(u));
    return r;
}
__device__ __forceinline__ void upk2(unsigned long long v, float& lo, float& hi) {
    unsigned int a, b;
    asm("mov.b64 {%0, %1}, %2;" : "=r"(a), "=r"(b) : "l"(v));
    lo = __uint_as_float(a);
    hi = __uint_as_float(b);
}
__device__ __forceinline__ float ex2f(float x) {          // guaranteed single MUFU
    float y;
    asm("ex2.approx.ftz.f32 %0, %1;" : "=f"(y) : "f"(x));
    return y;
}
__device__ __forceinline__ unsigned int h2bits(__half2 h) {
    return *(unsigned int*)&h;
}

__device__ __forceinline__ int detect64(const unsigned int* w) {
    int is64 = 1;
    for (int j = 1; j < 64; j += 2)
        if (w[j] != 0u) { is64 = 0; break; }
    return is64;
}

__device__ __forceinline__ int edge_val(const void* ei, long long flat, int is64) {
    if (is64) return (int)((const long long*)ei)[flat];
    return ((const int*)ei)[flat];
}

// ---------------- hist: 2 edges/thread, rank recording + 8-way partials ----------------
__global__ void k_hist(const void* __restrict__ ei) {
    int g = blockIdx.x * blockDim.x + threadIdx.x;   // NE/2 threads
    if (g >= NE / 2) return;
    int is64 = g_is64;
    if (is64 < 0) is64 = detect64((const unsigned int*)ei);   // call-1 self-detect
    int e0 = g * 2;
    int d0, d1;
    if (is64) {
        d0 = edge_val(ei, (long long)NE + e0, 1);
        d1 = edge_val(ei, (long long)NE + e0 + 1, 1);
    } else {
        int2 dd = ((const int2*)ei)[NE / 2 + g];
        d0 = dd.x; d1 = dd.y;
    }
    int p0 = e0 & (NPART - 1);
    int p1 = (e0 + 1) & (NPART - 1);
    int r0 = atomicAdd(&g_deg[p0 * NN + d0], 1);
    int r1 = atomicAdd(&g_deg[p1 * NN + d1], 1);
    *(int2*)&g_rank[e0] = make_int2(r0, r1);
}

// ---------------- scan: 4 nodes/thread, int4 vectorized ----------------
__global__ void k_scan() {
    __shared__ int warpsum[32];
    __shared__ int carry;
    int tid = threadIdx.x, lane = tid & 31, wid = tid >> 5;
    if (tid == 0) { carry = 0; g_rowptr[0] = 0; }
    __syncthreads();
    for (int base = 0; base < NN; base += 4096) {
        int i0 = base + tid * 4;
        bool ok = i0 < NN;                    // NN % 4 == 0
        int4 d[NPART];
        int v0 = 0, v1 = 0, v2 = 0, v3 = 0;
#pragma unroll
        for (int p = 0; p < NPART; p++) {
            d[p] = ok ? *(const int4*)&g_deg[p * NN + i0] : make_int4(0, 0, 0, 0);
            v0 += d[p].x; v1 += d[p].y; v2 += d[p].z; v3 += d[p].w;
        }
        int v = v0 + v1 + v2 + v3;
        int s = v;
#pragma unroll
        for (int off = 1; off < 32; off <<= 1) {
            int t = __shfl_up_sync(0xffffffffu, s, off);
            if (lane >= off) s += t;
        }
        if (lane == 31) warpsum[wid] = s;
        __syncthreads();
        if (wid == 0) {
            int ws = warpsum[lane];
            int ss = ws;
#pragma unroll
            for (int off = 1; off < 32; off <<= 1) {
                int t = __shfl_up_sync(0xffffffffu, ss, off);
                if (lane >= off) ss += t;
            }
            warpsum[lane] = ss - ws;
        }
        __syncthreads();
        int incl = s + warpsum[wid] + carry;
        if (ok) {
            int b0 = incl - v;
            int b1 = b0 + v0, b2 = b1 + v1, b3 = b2 + v2;
            g_rowptr[i0 + 1] = b1; g_rowptr[i0 + 2] = b2;
            g_rowptr[i0 + 3] = b3; g_rowptr[i0 + 4] = b3 + v3;
            int c0 = b0, c1 = b1, c2 = b2, c3 = b3;
#pragma unroll
            for (int p = 0; p < NPART; p++) {
                *(int4*)&g_cur[p * NN + i0] = make_int4(c0, c1, c2, c3);
                c0 += d[p].x; c1 += d[p].y; c2 += d[p].z; c3 += d[p].w;
            }
        }
        __syncthreads();
        if (tid == 1023) carry = incl;
        __syncthreads();
    }
}

// ---------------- fill: 4 edges/thread, no atomics ----------------
__global__ void k_fill(const void* __restrict__ ei) {
    int g = blockIdx.x * blockDim.x + threadIdx.x;   // NE/4 threads
    if (g >= NE / 4) return;
    int is64 = g_is64;
    if (is64 < 0) is64 = detect64((const unsigned int*)ei);
    int e0 = g * 4;
    int src[4], dst[4], rk[4];
    if (is64) {
#pragma unroll
        for (int q = 0; q < 4; q++) {
            src[q] = edge_val(ei, e0 + q, 1);
            dst[q] = edge_val(ei, (long long)NE + e0 + q, 1);
        }
    } else {
        int4 s4 = ((const int4*)ei)[g];
        int4 d4 = ((const int4*)ei)[NE / 4 + g];
        src[0] = s4.x; src[1] = s4.y; src[2] = s4.z; src[3] = s4.w;
        dst[0] = d4.x; dst[1] = d4.y; dst[2] = d4.z; dst[3] = d4.w;
    }
    int4 r4 = ((const int4*)g_rank)[g];
    rk[0] = r4.x; rk[1] = r4.y; rk[2] = r4.z; rk[3] = r4.w;
    int pos[4];
#pragma unroll
    for (int q = 0; q < 4; q++) {
        int part = (e0 + q) & (NPART - 1);
        pos[q] = g_cur[part * NN + dst[q]] + rk[q];
    }
#pragma unroll
    for (int q = 0; q < 4; q++) g_csrc[pos[q]] = src[q];
}

// ---------------- GEMM: 512 threads, 4 row-pairs x 4 cols/thread, f32x2 ----------------
__global__ __launch_bounds__(512, 2) void k_gemm(const float* __restrict__ x,
                                                 const float* __restrict__ W,
                                                 const float* __restrict__ att_src,
                                                 const float* __restrict__ att_dst) {
    __shared__ float xs[32][136];   // [k][row], padded
    __shared__ float ws[32][132];   // [k][col], padded
    int tid = threadIdx.x;
    int lane = tid & 31;
    int row0 = blockIdx.x * 128;
    int r0 = (tid >> 5) * 8;        // 8 rows = 4 pairs per warp
    int c0 = lane * 4;

    unsigned long long acc[4][4];
#pragma unroll
    for (int i = 0; i < 4; i++)
#pragma unroll
        for (int j = 0; j < 4; j++) acc[i][j] = 0ull;

#pragma unroll 1
    for (int kk = 0; kk < 128; kk += 32) {
        {   // W tile: 32 k-rows x 128 cols; 8 floats/thread
            int lk = tid >> 4;
            int lc = (tid & 15) * 8;
            const float4* wp = (const float4*)(W + (size_t)(kk + lk) * 128 + lc);
            float4* q = (float4*)&ws[lk][lc];
            q[0] = wp[0]; q[1] = wp[1];
        }
        {   // x tile: 128 rows x 32 k, transposed; 8 k-values/thread
            int lr = tid >> 2;
            int k0 = (tid & 3) * 8;
            int grow = row0 + lr; if (grow >= NN) grow = NN - 1;
            const float* xp = x + (size_t)grow * 128 + kk + k0;
            float4 a = *(const float4*)xp;
            float4 b = *(const float4*)(xp + 4);
            xs[k0 + 0][lr] = a.x; xs[k0 + 1][lr] = a.y;
            xs[k0 + 2][lr] = a.z; xs[k0 + 3][lr] = a.w;
            xs[k0 + 4][lr] = b.x; xs[k0 + 5][lr] = b.y;
            xs[k0 + 6][lr] = b.z; xs[k0 + 7][lr] = b.w;
        }
        __syncthreads();
#pragma unroll 2
        for (int k = 0; k < 32; k++) {
            ulonglong2 xpA = *(const ulonglong2*)&xs[k][r0];      // pairs 0,1
            ulonglong2 xpB = *(const ulonglong2*)&xs[k][r0 + 4];  // pairs 2,3
            float4 wv = *(const float4*)&ws[k][c0];
            unsigned long long wd0 = pk2(wv.x), wd1 = pk2(wv.y);
            unsigned long long wd2 = pk2(wv.z), wd3 = pk2(wv.w);
            unsigned long long xp[4] = {xpA.x, xpA.y, xpB.x, xpB.y};
#pragma unroll
            for (int i = 0; i < 4; i++) {
                FMA2(acc[i][0], xp[i], wd0, acc[i][0]);
                FMA2(acc[i][1], xp[i], wd1, acc[i][1]);
                FMA2(acc[i][2], xp[i], wd2, acc[i][2]);
                FMA2(acc[i][3], xp[i], wd3, acc[i][3]);
            }
        }
        __syncthreads();
    }

    // epilogue: fp16 xl + attention logits scaled by log2(e)
    float4 asv = ((const float4*)att_src)[lane];
    float4 adv = ((const float4*)att_dst)[lane];
    int head = lane >> 2;
#pragma unroll
    for (int i = 0; i < 4; i++) {
        float a0, b0, a1, b1, a2, b2, a3, b3;   // a*=even row, b*=odd row
        upk2(acc[i][0], a0, b0); upk2(acc[i][1], a1, b1);
        upk2(acc[i][2], a2, b2); upk2(acc[i][3], a3, b3);
#pragma unroll
        for (int par = 0; par < 2; par++) {
            float o0 = par ? b0 : a0, o1 = par ? b1 : a1;
            float o2 = par ? b2 : a2, o3 = par ? b3 : a3;
            int r = row0 + r0 + 2 * i + par;
            float ps = o0 * asv.x + o1 * asv.y + o2 * asv.z + o3 * asv.w;
            float pd = o0 * adv.x + o1 * adv.y + o2 * adv.z + o3 * adv.w;
            ps += __shfl_xor_sync(0xffffffffu, ps, 1);
            ps += __shfl_xor_sync(0xffffffffu, ps, 2);
            pd += __shfl_xor_sync(0xffffffffu, pd, 1);
            pd += __shfl_xor_sync(0xffffffffu, pd, 2);
            if (r < NN) {
                __half2 p0 = __float22half2_rn(make_float2(o0, o1));
                __half2 p1 = __float22half2_rn(make_float2(o2, o3));
                uint2 u;
                u.x = h2bits(p0);
                u.y = h2bits(p1);
                ((uint2*)g_xlh)[(size_t)r * 32 + lane] = u;
                if ((lane & 3) == 0) {
                    g_asrc[r * 8 + head] = ps * LOG2E;
                    g_adst[r * 8 + head] = pd * LOG2E;
                }
            }
        }
    }
}

// ---------------- warp-per-dst aggregation: 4 edges in flight x 8 lanes/edge ----------
// lane = grp*8 + lc; grp in [0,4) = edge stream parity; lc in [0,8) = head index,
// covering channels 16lc..16lc+15 (= one full head -> ONE asrc/ex2/denom per lane-edge).
__global__ __launch_bounds__(256) void k_agg(const float* __restrict__ bias) {
    __shared__ float ss[8][136];
    __shared__ float sq[8][136];
    int g = blockIdx.x * blockDim.x + threadIdx.x;
    int w = g >> 5;
    int lane = g & 31;
    int wid = threadIdx.x >> 5;
    int grp = lane >> 3;       // edge stream 0..3
    int lc = lane & 7;         // head; channels 16lc..16lc+15

    float A[16];
#pragma unroll
    for (int i = 0; i < 16; i++) A[i] = 0.f;
    float o[16];
#pragma unroll
    for (int i = 0; i < 16; i++) o[i] = 0.f;
    float denom = 0.f;

    if (w < NN) {
        int start = g_rowptr[w], end = g_rowptr[w + 1];
        float adst = g_adst[w * 8 + lc];
        const char* xlb = (const char*)g_xlh + (unsigned)(lc * 32);  // 32B per lane
        const float* asp = g_asrc + lc;

        int j = start + grp;                       // lane-private edge stream, stride 4
#pragma unroll 2
        while (j < end) {
            int src = __ldg(&g_csrc[j]);
            float e = __ldg(asp + src * 8) + adst;
            e = fmaxf(e, 0.2f * e);                 // leaky relu (pre-scaled by log2e)
            float wq = ex2f(e);
            const uint4* p = (const uint4*)(xlb + ((unsigned)src << 8));
            uint4 u0 = __ldg(p);                    // channels 16lc..+7
            uint4 u1 = __ldg(p + 1);                // channels 16lc+8..+15
            float2 f;
            f = __half22float2(*(__half2*)&u0.x); A[0] = fmaf(wq, f.x, A[0]);  A[1] = fmaf(wq, f.y, A[1]);
            f = __half22float2(*(__half2*)&u0.y); A[2] = fmaf(wq, f.x, A[2]);  A[3] = fmaf(wq, f.y, A[3]);
            f = __half22float2(*(__half2*)&u0.z); A[4] = fmaf(wq, f.x, A[4]);  A[5] = fmaf(wq, f.y, A[5]);
            f = __half22float2(*(__half2*)&u0.w); A[6] = fmaf(wq, f.x, A[6]);  A[7] = fmaf(wq, f.y, A[7]);
            f = __half22float2(*(__half2*)&u1.x); A[8] = fmaf(wq, f.x, A[8]);  A[9] = fmaf(wq, f.y, A[9]);
            f = __half22float2(*(__half2*)&u1.y); A[10] = fmaf(wq, f.x, A[10]); A[11] = fmaf(wq, f.y, A[11]);
            f = __half22float2(*(__half2*)&u1.z); A[12] = fmaf(wq, f.x, A[12]); A[13] = fmaf(wq, f.y, A[13]);
            f = __half22float2(*(__half2*)&u1.w); A[14] = fmaf(wq, f.x, A[14]); A[15] = fmaf(wq, f.y, A[15]);
            denom += wq;
            j += 4;
        }
        // merge the 4 edge streams (xor 8 pairs grp 0<->1 / 2<->3; xor 16 pairs across)
        denom += __shfl_xor_sync(0xffffffffu, denom, 8);
        denom += __shfl_xor_sync(0xffffffffu, denom, 16);
#pragma unroll
        for (int i = 0; i < 16; i++) {
            A[i] += __shfl_xor_sync(0xffffffffu, A[i], 8);
            A[i] += __shfl_xor_sync(0xffffffffu, A[i], 16);
        }
        float inv = 1.f / (denom + 1e-16f);
        float4 b0 = ((const float4*)bias)[lc * 4];
        float4 b1 = ((const float4*)bias)[lc * 4 + 1];
        float4 b2 = ((const float4*)bias)[lc * 4 + 2];
        float4 b3 = ((const float4*)bias)[lc * 4 + 3];
        o[0]  = fmaf(A[0],  inv, b0.x); o[1]  = fmaf(A[1],  inv, b0.y);
        o[2]  = fmaf(A[2],  inv, b0.z); o[3]  = fmaf(A[3],  inv, b0.w);
        o[4]  = fmaf(A[4],  inv, b1.x); o[5]  = fmaf(A[5],  inv, b1.y);
        o[6]  = fmaf(A[6],  inv, b1.z); o[7]  = fmaf(A[7],  inv, b1.w);
        o[8]  = fmaf(A[8],  inv, b2.x); o[9]  = fmaf(A[9],  inv, b2.y);
        o[10] = fmaf(A[10], inv, b2.z); o[11] = fmaf(A[11], inv, b2.w);
        o[12] = fmaf(A[12], inv, b3.x); o[13] = fmaf(A[13], inv, b3.y);
        o[14] = fmaf(A[14], inv, b3.z); o[15] = fmaf(A[15], inv, b3.w);
        if (grp == 0) {
            uint4 st0, st1;
            st0.x = h2bits(__float22half2_rn(make_float2(o[0], o[1])));
            st0.y = h2bits(__float22half2_rn(make_float2(o[2], o[3])));
            st0.z = h2bits(__float22half2_rn(make_float2(o[4], o[5])));
            st0.w = h2bits(__float22half2_rn(make_float2(o[6], o[7])));
            st1.x = h2bits(__float22half2_rn(make_float2(o[8], o[9])));
            st1.y = h2bits(__float22half2_rn(make_float2(o[10], o[11])));
            st1.z = h2bits(__float22half2_rn(make_float2(o[12], o[13])));
            st1.w = h2bits(__float22half2_rn(make_float2(o[14], o[15])));
            ((uint4*)g_hh)[(size_t)w * 16 + lc * 2] = st0;
            ((uint4*)g_hh)[(size_t)w * 16 + lc * 2 + 1] = st1;
        }
    }

    // fused BN partial stats: grp-0 lanes (8) cover all 128 channels of this warp's node
    if (grp == 0) {
#pragma unroll
        for (int k = 0; k < 4; k++) {
            float4 v = {o[k * 4], o[k * 4 + 1], o[k * 4 + 2], o[k * 4 + 3]};
            float4 q = {v.x * v.x, v.y * v.y, v.z * v.z, v.w * v.w};
            *(float4*)&ss[wid][lc * 16 + k * 4] = v;
            *(float4*)&sq[wid][lc * 16 + k * 4] = q;
        }
    }
    __syncthreads();
    int tid = threadIdx.x;
    if (tid < 128) {
        float s = 0.f, q = 0.f;
#pragma unroll
        for (int ww = 0; ww < 8; ww++) { s += ss[ww][tid]; q += sq[ww][tid]; }
        int slot = blockIdx.x & (NSLOT - 1);
        atomicAdd(&g_ps1[slot * 128 + tid], s);
        atomicAdd(&g_ps2[slot * 128 + tid], q);
    }
}

// ---------------- BN params: 1024 threads, parallel slot reduction ----------------
__global__ void k_bnp(const float* __restrict__ gamma,
                      const float* __restrict__ beta) {
    __shared__ float s1[1024], s2[1024];
    int tid = threadIdx.x;
    int c = tid & 127;
    int grp = tid >> 7;                 // 0..7, each covers 8 slots
    float s = 0.f, q = 0.f;
#pragma unroll
    for (int k = 0; k < 8; k++) {
        int slot = grp * 8 + k;
        s += g_ps1[slot * 128 + c];
        q += g_ps2[slot * 128 + c];
    }
    s1[tid] = s; s2[tid] = q;
    __syncthreads();
    if (tid < 128) {
        double S = 0.0, Q = 0.0;
#pragma unroll
        for (int r = 0; r < 8; r++) { S += (double)s1[tid + r * 128]; Q += (double)s2[tid + r * 128]; }
        double mean_d = S / (double)NN;
        double var_d = Q / (double)NN - mean_d * mean_d;
        float sc = gamma[tid] * rsqrtf((float)var_d + 1e-5f);
        g_scale[tid] = sc;
        g_shift[tid] = beta[tid] - (float)mean_d * sc;
    }
}

// ---------------- normalize + ReLU + residual + next-call housekeeping ----------------
__global__ void k_final(const float* __restrict__ x, float* __restrict__ out,
                        const unsigned int* __restrict__ ei) {
    int g = blockIdx.x * blockDim.x + threadIdx.x;   // NN*16 uint4s (8 channels each)
    if (g < NPART * NN) g_deg[g] = 0;
    if (g < NSLOT * 128) { g_ps1[g] = 0.f; g_ps2[g] = 0.f; }
    if (g == 0) g_is64 = detect64(ei);
    if (g >= NN * 16) return;
    int l = g & 15;                                  // channels l*8 .. l*8+7
    uint4 u = ((const uint4*)g_hh)[g];
    float2 f0 = __half22float2(*(__half2*)&u.x);
    float2 f1 = __half22float2(*(__half2*)&u.y);
    float2 f2 = __half22float2(*(__half2*)&u.z);
    float2 f3 = __half22float2(*(__half2*)&u.w);
    float4 xv0 = ((const float4*)x)[g * 2];
    float4 xv1 = ((const float4*)x)[g * 2 + 1];
    float4 sc0 = ((const float4*)g_scale)[l * 2];
    float4 sc1 = ((const float4*)g_scale)[l * 2 + 1];
    float4 sh0 = ((const float4*)g_shift)[l * 2];
    float4 sh1 = ((const float4*)g_shift)[l * 2 + 1];
    float4 o0, o1;
    o0.x = xv0.x + fmaxf(0.f, fmaf(f0.x, sc0.x, sh0.x));
    o0.y = xv0.y + fmaxf(0.f, fmaf(f0.y, sc0.y, sh0.y));
    o0.z = xv0.z + fmaxf(0.f, fmaf(f1.x, sc0.z, sh0.z));
    o0.w = xv0.w + fmaxf(0.f, fmaf(f1.y, sc0.w, sh0.w));
    o1.x = xv1.x + fmaxf(0.f, fmaf(f2.x, sc1.x, sh1.x));
    o1.y = xv1.y + fmaxf(0.f, fmaf(f2.y, sc1.y, sh1.y));
    o1.z = xv1.z + fmaxf(0.f, fmaf(f3.x, sc1.z, sh1.z));
    o1.w = xv1.w + fmaxf(0.f, fmaf(f3.y, sc1.w, sh1.w));
    ((float4*)out)[g * 2] = o0;
    ((float4*)out)[g * 2 + 1] = o1;
}

// ---------------- launch: CSR build forked onto a side stream, overlapped with GEMM --------
extern "C" void kernel_launch(void* const* d_in, const int* in_sizes, int n_in,
                              void* d_out, int out_size) {
    const float* x       = (const float*)d_in[0];
    const void*  ei      = d_in[1];
    const float* W       = (const float*)d_in[2];
    const float* att_src = (const float*)d_in[3];
    const float* att_dst = (const float*)d_in[4];
    const float* bias    = (const float*)d_in[5];
    const float* gamma   = (const float*)d_in[6];
    const float* beta    = (const float*)d_in[7];
    float* out = (float*)d_out;
    (void)in_sizes; (void)n_in; (void)out_size;

    const int WB = (NN * 32 + 255) / 256;     // 6250 (agg)
    const int FB = (NN * 16 + 255) / 256;     // 3125 (final)

    cudaStream_t sB;
    cudaEvent_t eF, eJ;
    cudaStreamCreateWithFlags(&sB, cudaStreamNonBlocking);
    cudaEventCreateWithFlags(&eF, cudaEventDisableTiming);
    cudaEventCreateWithFlags(&eJ, cudaEventDisableTiming);

    cudaEventRecord(eF, 0);                  // fork from the (captured) main stream
    cudaStreamWaitEvent(sB, eF, 0);

    // side stream: CSR build (independent of GEMM)
    k_hist <<<(NE / 2 + 255) / 256, 256, 0, sB>>>(ei);
    k_scan <<<1, 1024, 0, sB>>>();
    k_fill <<<(NE / 4 + 255) / 256, 256, 0, sB>>>(ei);
    cudaEventRecord(eJ, sB);

    // main stream: GEMM concurrently
    k_gemm <<<(NN + 127) / 128, 512>>>(x, W, att_src, att_dst);

    cudaStreamWaitEvent(0, eJ, 0);           // join
    k_agg  <<<WB, 256>>>(bias);
    k_bnp  <<<1, 1024>>>(gamma, beta);
    k_final<<<FB, 256>>>(x, out, (const unsigned int*)ei);
}